// round 2
// baseline (speedup 1.0000x reference)
#include <cuda_runtime.h>
#include <cstdint>

#define NB 32
#define NCh 128
#define NHW 16
#define NV 8192
#define NELEM (NB*NCh*NHW*NHW)   // 1048576
#define NPOS  (NB*NHW*NHW)       // 8192
#define NSLAB 16                 // 8192 / 512

// ---------------- persistent device scratch (no allocation allowed) ----------------
__device__ float g_frest[NELEM];             // NHWC
__device__ float g_fhat[NELEM];              // NHWC
__device__ float g_rest[NPOS*NCh];           // [N][128] query rows
__device__ float g_h[NELEM];                 // NHWC  (upsampled code field)
__device__ float g_h2[NELEM];                // NHWC  (after Phi)
__device__ float g_half_esq[NV];
__device__ float g_pscore[NPOS*NSLAB];
__device__ int   g_pidx[NPOS*NSLAB];
__device__ int   g_idx[NPOS];
__device__ float g_wT[4*NCh*NCh*9];          // [k][ci][ky][kx][co]
__device__ float g_Wall[5*16*16];            // resize weight matrices per stage
__device__ float g_sse[8];
__device__ int   g_swap;                     // 0: cand0 is f, 1: cand0 is embedding

// ---------------- input disambiguation (f vs embedding have equal sizes) ----------------
__global__ void k_detect(const float* __restrict__ a) {
    __shared__ float red[256];
    int t = threadIdx.x;
    float s = 0.f;
    #pragma unroll 4
    for (int k = 0; k < 64; k++) { float x = a[t + 256*k]; s += x*x; }
    red[t] = s; __syncthreads();
    for (int m = 128; m > 0; m >>= 1) { if (t < m) red[t] += red[t+m]; __syncthreads(); }
    // mean square of f ~ 1.0, of embedding ~ 0.25 over 16384 samples
    if (t == 0) g_swap = (red[0] > 0.5f * 16384.f) ? 0 : 1;
}

// ---------------- init kernels ----------------
__global__ void k_init_transpose(const float* __restrict__ a, const float* __restrict__ b) {
    const float* f = g_swap ? b : a;
    int i = blockIdx.x*blockDim.x + threadIdx.x;
    if (i < 8) g_sse[i] = 0.f;
    if (i >= NELEM) return;
    int bb = i >> 15;            // /(128*256)
    int c  = (i >> 8) & 127;
    int yx = i & 255;
    int nh = ((((bb << 8) | yx) << 7) | c);
    g_frest[nh] = f[i];
    g_fhat[nh]  = 0.f;
}

__global__ void k_init_esq(const float* __restrict__ a, const float* __restrict__ b) {
    const float* emb = g_swap ? a : b;
    int v = blockIdx.x;
    int t = threadIdx.x;  // 128
    float x = emb[v*NCh + t];
    float s = x*x;
    #pragma unroll
    for (int m = 16; m > 0; m >>= 1) s += __shfl_xor_sync(0xffffffffu, s, m);
    __shared__ float ws[4];
    if ((t & 31) == 0) ws[t >> 5] = s;
    __syncthreads();
    if (t == 0) g_half_esq[v] = 0.5f*(ws[0]+ws[1]+ws[2]+ws[3]);
}

__global__ void k_init_wtrans(const float* __restrict__ phi_w) {
    int o = blockIdx.x*blockDim.x + threadIdx.x;
    if (o >= 4*NCh*NCh*9) return;
    int co = o & 127;
    int r  = o >> 7;
    int kx = r % 3; r /= 3;
    int ky = r % 3; r /= 3;
    int ci = r & 127;
    int k  = r >> 7;
    g_wT[o] = phi_w[(((k*NCh + co)*NCh + ci)*3 + ky)*3 + kx];
}

__device__ __forceinline__ double keys_cubic(double x) {
    x = fabs(x);
    if (x < 1.0) return ((1.5*x - 2.5)*x)*x + 1.0;
    if (x < 2.0) return ((-0.5*x + 2.5)*x - 4.0)*x + 2.0;
    return 0.0;
}

// JAX compute_weight_mat: sample=(i+0.5)*in/out-0.5; Keys a=-0.5; column-normalized.
__global__ void k_init_resizew() {
    int t = threadIdx.x;     // need 80
    if (t >= 80) return;
    const int pns[5] = {1,2,4,8,16};
    int si = t >> 4, i = t & 15;
    int pn = pns[si];
    double sample = (i + 0.5) * (double)pn / 16.0 - 0.5;
    double w[16]; double tot = 0.0;
    for (int j = 0; j < 16; j++) w[j] = 0.0;
    for (int j = 0; j < pn; j++) { w[j] = keys_cubic(sample - (double)j); tot += w[j]; }
    for (int j = 0; j < 16; j++) g_Wall[(si*16 + i)*16 + j] = (float)(w[j] / tot);
}

// ---------------- stage kernels ----------------
// grid = N blocks, 128 threads.
__global__ void k_pool(int pn) {
    int n = blockIdx.x;
    int c = threadIdx.x;
    int s = 16 / pn;
    int pp = pn*pn;
    int b   = n / pp;
    int rem = n - b*pp;
    int py = rem / pn, px = rem - py*pn;
    float acc = 0.f;
    int y0 = py*s, x0 = px*s;
    for (int dy = 0; dy < s; dy++)
        for (int dx = 0; dx < s; dx++)
            acc += g_frest[(((b*16 + y0+dy)*16) + (x0+dx))*128 + c];
    g_rest[n*128 + c] = acc / (float)(s*s);
}

// NN search: argmax over V of (dot(r,e) - 0.5|e|^2)  <=>  argmin distance.
// block tile: 64 rows x 512-codes slab (8 inner iters of 64 codes), 4x4 regs/thread.
// per-(row,slab) best written to g_pscore/g_pidx; merged by k_argmerge.
__global__ __launch_bounds__(256) void k_nn(const float* __restrict__ a_,
                                            const float* __restrict__ b_, int N) {
    const float* emb = g_swap ? a_ : b_;
    extern __shared__ float sm[];
    float* As = sm;              // 64 x 132
    float* Es = sm + 64*132;     // 64 x 132
    int r0    = blockIdx.x * 64;
    int vbase = blockIdx.y * 512;
    int t = threadIdx.x;

    #pragma unroll
    for (int q = 0; q < 8; q++) {
        int idx4 = t + q*256;
        int row = idx4 >> 5;
        int k4  = idx4 & 31;
        float4 v = make_float4(0.f,0.f,0.f,0.f);
        int gr = r0 + row;
        if (gr < N) v = reinterpret_cast<const float4*>(g_rest + (size_t)gr*128)[k4];
        *reinterpret_cast<float4*>(&As[row*132 + k4*4]) = v;
    }

    int tm = t >> 4, tv = t & 15;
    float bs[4]; int bi[4];
    #pragma unroll
    for (int i = 0; i < 4; i++) { bs[i] = -3.4e38f; bi[i] = 0x7fffffff; }

    for (int it = 0; it < 8; it++) {
        int v0 = vbase + it*64;
        __syncthreads();
        #pragma unroll
        for (int q = 0; q < 8; q++) {
            int idx4 = t + q*256;
            int row = idx4 >> 5;
            int k4  = idx4 & 31;
            float4 v = reinterpret_cast<const float4*>(emb + (size_t)(v0+row)*128)[k4];
            *reinterpret_cast<float4*>(&Es[row*132 + k4*4]) = v;
        }
        __syncthreads();

        float acc[4][4];
        #pragma unroll
        for (int i = 0; i < 4; i++)
            #pragma unroll
            for (int j = 0; j < 4; j++) acc[i][j] = 0.f;

        #pragma unroll 8
        for (int k = 0; k < 128; k += 4) {
            float4 a[4], e[4];
            #pragma unroll
            for (int i = 0; i < 4; i++) a[i] = *reinterpret_cast<float4*>(&As[(tm*4+i)*132 + k]);
            #pragma unroll
            for (int j = 0; j < 4; j++) e[j] = *reinterpret_cast<float4*>(&Es[(tv*4+j)*132 + k]);
            #pragma unroll
            for (int i = 0; i < 4; i++)
                #pragma unroll
                for (int j = 0; j < 4; j++) {
                    acc[i][j] += a[i].x*e[j].x;
                    acc[i][j] += a[i].y*e[j].y;
                    acc[i][j] += a[i].z*e[j].z;
                    acc[i][j] += a[i].w*e[j].w;
                }
        }

        #pragma unroll
        for (int j = 0; j < 4; j++) {
            int col = v0 + tv*4 + j;
            float hs = g_half_esq[col];
            #pragma unroll
            for (int i = 0; i < 4; i++) {
                float s = acc[i][j] - hs;
                if (s > bs[i] || (s == bs[i] && col < bi[i])) { bs[i] = s; bi[i] = col; }
            }
        }
    }

    // reduce over the 16 tv lanes (stays inside each 16-lane group)
    #pragma unroll
    for (int m = 8; m >= 1; m >>= 1)
        #pragma unroll
        for (int i = 0; i < 4; i++) {
            float os = __shfl_xor_sync(0xffffffffu, bs[i], m);
            int   oi = __shfl_xor_sync(0xffffffffu, bi[i], m);
            if (os > bs[i] || (os == bs[i] && oi < bi[i])) { bs[i] = os; bi[i] = oi; }
        }
    if (tv == 0) {
        #pragma unroll
        for (int i = 0; i < 4; i++) {
            int gr = r0 + tm*4 + i;
            if (gr < N) {
                g_pscore[gr*NSLAB + blockIdx.y] = bs[i];
                g_pidx  [gr*NSLAB + blockIdx.y] = bi[i];
            }
        }
    }
}

__global__ void k_argmerge(int N) {
    int r = blockIdx.x*256 + threadIdx.x;
    if (r >= N) return;
    float bs = g_pscore[r*NSLAB]; int bi = g_pidx[r*NSLAB];
    #pragma unroll
    for (int s = 1; s < NSLAB; s++) {
        float os = g_pscore[r*NSLAB + s]; int oi = g_pidx[r*NSLAB + s];
        if (os > bs || (os == bs && oi < bi)) { bs = os; bi = oi; }
    }
    g_idx[r] = bi;
}

// gather + separable-cubic upsample (pn=16 has identity weights -> pure gather)
__global__ void k_upsample(const float* __restrict__ a_, const float* __restrict__ b_,
                           int pn, int si) {
    const float* emb = g_swap ? a_ : b_;
    int blk = blockIdx.x;   // 8192 = (b,Y,X)
    int c = threadIdx.x;    // 128
    int b = blk >> 8;
    int Y = (blk >> 4) & 15;
    int X = blk & 15;
    const float* Wm = g_Wall + si*256;
    float acc = 0.f;
    for (int py = 0; py < pn; py++) {
        float wy = Wm[Y*16 + py];
        if (wy == 0.f) continue;
        for (int px = 0; px < pn; px++) {
            float wx = Wm[X*16 + px];
            if (wx == 0.f) continue;
            int n = (b*pn + py)*pn + px;
            int id = g_idx[n];
            acc += (wy*wx) * emb[(size_t)id*128 + c];
        }
    }
    g_h[(size_t)blk*128 + c] = acc;
}

// Phi: out = 0.5*h + 0.5*(conv3x3(h)+bias). grid (16 rows, 32 batch), 128 thr = co.
__global__ __launch_bounds__(128) void k_conv(const float* __restrict__ bias, int kphi) {
    __shared__ float s_in[3][18][128];
    int y  = blockIdx.x;
    int b  = blockIdx.y;
    int co = threadIdx.x;
    const float* wTk = g_wT + (size_t)kphi*(NCh*NCh*9);

    #pragma unroll
    for (int ky = 0; ky < 3; ky++) {
        int yy = y + ky - 1;
        #pragma unroll
        for (int xi = 0; xi < 18; xi++) {
            int xx = xi - 1;
            float v = 0.f;
            if (yy >= 0 && yy < 16 && xx >= 0 && xx < 16)
                v = g_h[((b*16+yy)*16+xx)*128 + co];
            s_in[ky][xi][co] = v;
        }
    }
    __syncthreads();

    float acc[16];
    #pragma unroll
    for (int x = 0; x < 16; x++) acc[x] = 0.f;

    for (int ci = 0; ci < 128; ci++) {
        #pragma unroll
        for (int ky = 0; ky < 3; ky++) {
            float row[18];
            #pragma unroll
            for (int xi = 0; xi < 18; xi++) row[xi] = s_in[ky][xi][ci];
            #pragma unroll
            for (int kx = 0; kx < 3; kx++) {
                float w = wTk[((ci*3+ky)*3+kx)*128 + co];
                #pragma unroll
                for (int x = 0; x < 16; x++) acc[x] += w * row[x+kx];
            }
        }
    }
    float bv = bias[co];
    #pragma unroll
    for (int x = 0; x < 16; x++) {
        float hval = s_in[1][x+1][co];
        g_h2[((b*16+y)*16+x)*128 + co] = 0.5f*hval + 0.5f*(acc[x] + bv);
    }
}

// f_hat += h2; f_rest -= h2; sse_si += (f_hat - f)^2
__global__ void k_update(const float* __restrict__ a_, const float* __restrict__ b_, int si) {
    const float* f = g_swap ? b_ : a_;
    int i = blockIdx.x*256 + threadIdx.x;
    float h  = g_h2[i];
    float fh = g_fhat[i] + h;
    g_fhat[i]  = fh;
    g_frest[i] -= h;
    int c  = i & 127;
    int p  = i >> 7;
    int b  = p >> 8;
    int yx = p & 255;
    float fv = f[((b*128 + c) << 8) | yx];
    float d = fh - fv;
    float s = d*d;
    #pragma unroll
    for (int m = 16; m > 0; m >>= 1) s += __shfl_xor_sync(0xffffffffu, s, m);
    __shared__ float ws[8];
    int t = threadIdx.x;
    if ((t & 31) == 0) ws[t >> 5] = s;
    __syncthreads();
    if (t < 8) {
        float x = ws[t];
        #pragma unroll
        for (int m = 4; m > 0; m >>= 1) x += __shfl_xor_sync(0xffu, x, m);
        if (t == 0) atomicAdd(&g_sse[si], x);
    }
}

__global__ void k_final(float* __restrict__ out) {
    int i = blockIdx.x*256 + threadIdx.x;
    int b  = i >> 15;
    int c  = (i >> 8) & 127;
    int yx = i & 255;
    out[i] = g_fhat[((((b << 8) | yx) << 7) | c)];
    if (i == 0) {
        float L = 0.f;
        for (int s = 0; s < 5; s++) L += 1.25f * (g_sse[s] / (float)NELEM);
        out[NELEM] = L / 5.f;
    }
}

// ---------------- launch ----------------
extern "C" void kernel_launch(void* const* d_in, const int* in_sizes, int n_in,
                              void* d_out, int out_size) {
    // resolve inputs by size: phi_w=589824, phi_b=512; the two 1048576 inputs are
    // f/embedding in unknown order (device-side probe disambiguates).
    const float* cand0 = nullptr; const float* cand1 = nullptr;
    const float* pw = nullptr;    const float* pb = nullptr;
    for (int i = 0; i < n_in; i++) {
        int s = in_sizes[i];
        const float* p = (const float*)d_in[i];
        if      (s == 4*NCh*NCh*9) pw = p;
        else if (s == 4*NCh)       pb = p;
        else if (!cand0)           cand0 = p;
        else                       cand1 = p;
    }
    float* out = (float*)d_out;

    const int nn_smem = 2 * 64 * 132 * (int)sizeof(float);  // 67.6 KB -> opt-in
    cudaFuncSetAttribute(k_nn, cudaFuncAttributeMaxDynamicSharedMemorySize, nn_smem);

    k_detect<<<1, 256>>>(cand0);
    k_init_transpose<<<4096, 256>>>(cand0, cand1);
    k_init_esq<<<NV, 128>>>(cand0, cand1);
    k_init_wtrans<<<2304, 256>>>(pw);
    k_init_resizew<<<1, 128>>>();

    const int pns[5]  = {1, 2, 4, 8, 16};
    const int kphi[5] = {0, 1, 2, 2, 3};   // fixed: float64 tick tie resolves to 2 at si=2

    for (int si = 0; si < 5; si++) {
        int pn = pns[si];
        int N  = NB * pn * pn;
        k_pool<<<N, 128>>>(pn);
        k_nn<<<dim3((N + 63)/64, NSLAB), 256, nn_smem>>>(cand0, cand1, N);
        k_argmerge<<<(N + 255)/256, 256>>>(N);
        k_upsample<<<NPOS, 128>>>(cand0, cand1, pn, si);
        k_conv<<<dim3(16, NB), 128>>>(pb + kphi[si]*NCh, kphi[si]);
        k_update<<<4096, 256>>>(cand0, cand1, si);
    }
    k_final<<<4096, 256>>>(out);
}

// round 3
// speedup vs baseline: 1.7828x; 1.7828x over previous
#include <cuda_runtime.h>
#include <cstdint>

#define NB 32
#define NCh 128
#define NHW 16
#define NV 8192
#define NELEM (NB*NCh*NHW*NHW)   // 1048576
#define NPOS  (NB*NHW*NHW)       // 8192

// ---------------- persistent device scratch (no allocation allowed) ----------------
__device__ float g_frest[NELEM];             // NHWC  (also the pn=16 query matrix)
__device__ float g_fhat[NELEM];              // NHWC
__device__ float g_rest[NPOS*NCh];           // [N][128] query rows
__device__ float g_h[NELEM];                 // NHWC  (upsampled code field)
__device__ float g_h2[NELEM];                // NHWC  (after Phi)
__device__ float g_half_esq[NV];
__device__ float g_pscore[NPOS*16];
__device__ int   g_pidx[NPOS*16];
__device__ int   g_idx[NPOS];
__device__ float g_wT2[4*9*64*256];          // [k][ky*3+kx][ci2][co*2+{lo,hi}]
__device__ float g_Wall[5*16*16];            // resize weight matrices per stage
__device__ float g_sse[8];
__device__ int   g_swap;                     // 0: cand0 is f, 1: cand0 is embedding

// ---------------- f32x2 packed helpers ----------------
__device__ __forceinline__ unsigned long long f2_pack(float x, float y) {
    unsigned long long r;
    asm("mov.b64 %0, {%1, %2};" : "=l"(r) : "f"(x), "f"(y));
    return r;
}
__device__ __forceinline__ void f2_unpack(unsigned long long v, float& x, float& y) {
    asm("mov.b64 {%0, %1}, %2;" : "=f"(x), "=f"(y) : "l"(v));
}
__device__ __forceinline__ unsigned long long ffma2(unsigned long long a,
                                                    unsigned long long b,
                                                    unsigned long long c) {
    unsigned long long d;
    asm("fma.rn.f32x2 %0, %1, %2, %3;" : "=l"(d) : "l"(a), "l"(b), "l"(c));
    return d;
}

// ---------------- input disambiguation (f vs embedding have equal sizes) ----------------
__global__ void k_detect(const float* __restrict__ a) {
    __shared__ float red[256];
    int t = threadIdx.x;
    float s = 0.f;
    #pragma unroll 4
    for (int k = 0; k < 64; k++) { float x = a[t + 256*k]; s += x*x; }
    red[t] = s; __syncthreads();
    for (int m = 128; m > 0; m >>= 1) { if (t < m) red[t] += red[t+m]; __syncthreads(); }
    // mean square of f ~ 1.0, of embedding ~ 0.25 over 16384 samples
    if (t == 0) g_swap = (red[0] > 0.5f * 16384.f) ? 0 : 1;
}

// ---------------- init kernels ----------------
__global__ void k_init_transpose(const float* __restrict__ a, const float* __restrict__ b) {
    const float* f = g_swap ? b : a;
    int i = blockIdx.x*blockDim.x + threadIdx.x;
    if (i < 8) g_sse[i] = 0.f;
    if (i >= NELEM) return;
    int bb = i >> 15;            // /(128*256)
    int c  = (i >> 8) & 127;
    int yx = i & 255;
    int nh = ((((bb << 8) | yx) << 7) | c);
    g_frest[nh] = f[i];
    g_fhat[nh]  = 0.f;
}

__global__ void k_init_esq(const float* __restrict__ a, const float* __restrict__ b) {
    const float* emb = g_swap ? a : b;
    int v = blockIdx.x;
    int t = threadIdx.x;  // 128
    float x = emb[v*NCh + t];
    float s = x*x;
    #pragma unroll
    for (int m = 16; m > 0; m >>= 1) s += __shfl_xor_sync(0xffffffffu, s, m);
    __shared__ float ws[4];
    if ((t & 31) == 0) ws[t >> 5] = s;
    __syncthreads();
    if (t == 0) g_half_esq[v] = 0.5f*(ws[0]+ws[1]+ws[2]+ws[3]);
}

// g_wT2[((k*9 + ky*3+kx)*64 + ci2)*256 + co*2 + p] = phi_w[k][co][ci2*2+p][ky][kx]
__global__ void k_init_wtrans(const float* __restrict__ phi_w) {
    int o = blockIdx.x*blockDim.x + threadIdx.x;
    if (o >= 4*NCh*NCh*9) return;
    int co2 = o & 255;
    int p  = co2 & 1;
    int co = co2 >> 1;
    int r  = o >> 8;
    int ci2 = r & 63; r >>= 6;
    int t9 = r % 9;
    int k  = r / 9;
    int ky = t9 / 3, kx = t9 % 3;
    int ci = ci2*2 + p;
    g_wT2[o] = phi_w[(((k*NCh + co)*NCh + ci)*3 + ky)*3 + kx];
}

__device__ __forceinline__ double keys_cubic(double x) {
    x = fabs(x);
    if (x < 1.0) return ((1.5*x - 2.5)*x)*x + 1.0;
    if (x < 2.0) return ((-0.5*x + 2.5)*x - 4.0)*x + 2.0;
    return 0.0;
}

// JAX compute_weight_mat: sample=(i+0.5)*in/out-0.5; Keys a=-0.5; column-normalized.
__global__ void k_init_resizew() {
    int t = threadIdx.x;     // need 80
    if (t >= 80) return;
    const int pns[5] = {1,2,4,8,16};
    int si = t >> 4, i = t & 15;
    int pn = pns[si];
    double sample = (i + 0.5) * (double)pn / 16.0 - 0.5;
    double w[16]; double tot = 0.0;
    for (int j = 0; j < 16; j++) w[j] = 0.0;
    for (int j = 0; j < pn; j++) { w[j] = keys_cubic(sample - (double)j); tot += w[j]; }
    for (int j = 0; j < 16; j++) g_Wall[(si*16 + i)*16 + j] = (float)(w[j] / tot);
}

// ---------------- stage kernels ----------------
// grid = N blocks, 128 threads. (not launched for pn==16)
__global__ void k_pool(int pn) {
    int n = blockIdx.x;
    int c = threadIdx.x;
    int s = 16 / pn;
    int pp = pn*pn;
    int b   = n / pp;
    int rem = n - b*pp;
    int py = rem / pn, px = rem - py*pn;
    float acc = 0.f;
    int y0 = py*s, x0 = px*s;
    for (int dy = 0; dy < s; dy++)
        for (int dx = 0; dx < s; dx++)
            acc += g_frest[(((b*16 + y0+dy)*16) + (x0+dx))*128 + c];
    g_rest[n*128 + c] = acc / (float)(s*s);
}

// NN search: argmax over V of (dot(r,e) - 0.5|e|^2)  <=>  argmin distance.
// block: 64 rows x 64-code inner tile, `iters` tiles per slab, f32x2 packed over k.
// per-(row,slab) best written to g_pscore/g_pidx; merged by k_argmerge.
__global__ __launch_bounds__(256) void k_nn(const float* __restrict__ a_,
                                            const float* __restrict__ b_,
                                            int N, int iters, int use_frest) {
    const float* emb = g_swap ? a_ : b_;
    extern __shared__ unsigned long long smu[];
    unsigned long long* Es2 = smu;                    // [64 k2][65] float2 per code
    float* As = (float*)(smu + 64*65);                // [64 rows][132] floats
    const float* R = use_frest ? g_frest : g_rest;

    int r0    = blockIdx.x * 64;
    int vbase = blockIdx.y * (iters * 64);
    int t = threadIdx.x;

    #pragma unroll
    for (int q = 0; q < 8; q++) {
        int idx4 = t + q*256;
        int row = idx4 >> 5;
        int k4  = idx4 & 31;
        float4 v = make_float4(0.f,0.f,0.f,0.f);
        int gr = r0 + row;
        if (gr < N) v = reinterpret_cast<const float4*>(R + (size_t)gr*128)[k4];
        *reinterpret_cast<float4*>(&As[row*132 + k4*4]) = v;
    }

    int tm = t >> 4, tv = t & 15;
    float bs[4]; int bi[4];
    #pragma unroll
    for (int i = 0; i < 4; i++) { bs[i] = -3.4e38f; bi[i] = 0x7fffffff; }

    for (int it = 0; it < iters; it++) {
        int v0 = vbase + it*64;
        __syncthreads();
        #pragma unroll
        for (int q = 0; q < 8; q++) {
            int idx4 = t + q*256;
            int code = idx4 & 63;
            int kc   = idx4 >> 6;      // 0..31 float4 chunks
            float4 v = reinterpret_cast<const float4*>(emb + (size_t)(v0+code)*128)[kc];
            Es2[(2*kc  )*65 + code] = f2_pack(v.x, v.y);
            Es2[(2*kc+1)*65 + code] = f2_pack(v.z, v.w);
        }
        __syncthreads();

        unsigned long long acc[4][4];
        #pragma unroll
        for (int i = 0; i < 4; i++)
            #pragma unroll
            for (int j = 0; j < 4; j++) acc[i][j] = 0ull;

        #pragma unroll 8
        for (int k2 = 0; k2 < 64; k2++) {
            unsigned long long a[4], e[4];
            #pragma unroll
            for (int i = 0; i < 4; i++)
                a[i] = *reinterpret_cast<const unsigned long long*>(&As[(tm*4+i)*132 + k2*2]);
            #pragma unroll
            for (int j = 0; j < 4; j++)
                e[j] = Es2[k2*65 + (tv + 16*j)];
            #pragma unroll
            for (int i = 0; i < 4; i++)
                #pragma unroll
                for (int j = 0; j < 4; j++)
                    acc[i][j] = ffma2(a[i], e[j], acc[i][j]);
        }

        #pragma unroll
        for (int j = 0; j < 4; j++) {
            int col = v0 + tv + 16*j;
            float hs = g_half_esq[col];
            #pragma unroll
            for (int i = 0; i < 4; i++) {
                float lo, hi;
                f2_unpack(acc[i][j], lo, hi);
                float s = (lo + hi) - hs;
                if (s > bs[i] || (s == bs[i] && col < bi[i])) { bs[i] = s; bi[i] = col; }
            }
        }
    }

    // reduce over the 16 tv lanes (stays inside each 16-lane group)
    #pragma unroll
    for (int m = 8; m >= 1; m >>= 1)
        #pragma unroll
        for (int i = 0; i < 4; i++) {
            float os = __shfl_xor_sync(0xffffffffu, bs[i], m);
            int   oi = __shfl_xor_sync(0xffffffffu, bi[i], m);
            if (os > bs[i] || (os == bs[i] && oi < bi[i])) { bs[i] = os; bi[i] = oi; }
        }
    if (tv == 0) {
        int gy = gridDim.y;
        #pragma unroll
        for (int i = 0; i < 4; i++) {
            int gr = r0 + tm*4 + i;
            if (gr < N) {
                g_pscore[gr*gy + blockIdx.y] = bs[i];
                g_pidx  [gr*gy + blockIdx.y] = bi[i];
            }
        }
    }
}

__global__ void k_argmerge(int N, int gy) {
    int r = blockIdx.x*256 + threadIdx.x;
    if (r >= N) return;
    float bs = g_pscore[r*gy]; int bi = g_pidx[r*gy];
    for (int s = 1; s < gy; s++) {
        float os = g_pscore[r*gy + s]; int oi = g_pidx[r*gy + s];
        if (os > bs || (os == bs && oi < bi)) { bs = os; bi = oi; }
    }
    g_idx[r] = bi;
}

// gather + separable-cubic upsample (pn=16 has identity weights -> pure gather)
__global__ void k_upsample(const float* __restrict__ a_, const float* __restrict__ b_,
                           int pn, int si) {
    const float* emb = g_swap ? a_ : b_;
    int blk = blockIdx.x;   // 8192 = (b,Y,X)
    int c = threadIdx.x;    // 128
    int b = blk >> 8;
    int Y = (blk >> 4) & 15;
    int X = blk & 15;
    const float* Wm = g_Wall + si*256;
    float acc = 0.f;
    for (int py = 0; py < pn; py++) {
        float wy = Wm[Y*16 + py];
        if (wy == 0.f) continue;
        for (int px = 0; px < pn; px++) {
            float wx = Wm[X*16 + px];
            if (wx == 0.f) continue;
            int n = (b*pn + py)*pn + px;
            int id = g_idx[n];
            acc += (wy*wx) * emb[(size_t)id*128 + c];
        }
    }
    g_h[(size_t)blk*128 + c] = acc;
}

// Phi: out = 0.5*h + 0.5*(conv3x3(h)+bias). grid (16 rows, 32 batch), 128 thr = co.
// ci-paired f32x2 accumulation: acc2[x] = {sum over even ci, sum over odd ci}.
__global__ __launch_bounds__(128) void k_conv(const float* __restrict__ bias, int kphi) {
    __shared__ float s_in[3][18][128];
    int y  = blockIdx.x;
    int b  = blockIdx.y;
    int co = threadIdx.x;
    const float* wbase = g_wT2 + (size_t)kphi*(9*64*256);

    #pragma unroll
    for (int ky = 0; ky < 3; ky++) {
        int yy = y + ky - 1;
        #pragma unroll
        for (int xi = 0; xi < 18; xi++) {
            int xx = xi - 1;
            float v = 0.f;
            if (yy >= 0 && yy < 16 && xx >= 0 && xx < 16)
                v = g_h[((b*16+yy)*16+xx)*128 + co];
            s_in[ky][xi][co] = v;
        }
    }
    __syncthreads();

    unsigned long long acc2[16];
    #pragma unroll
    for (int x = 0; x < 16; x++) acc2[x] = 0ull;

    for (int ci2 = 0; ci2 < 64; ci2++) {
        unsigned long long wv[9];
        #pragma unroll
        for (int t9 = 0; t9 < 9; t9++)
            wv[t9] = *reinterpret_cast<const unsigned long long*>(
                         wbase + ((size_t)(t9*64 + ci2)*256 + co*2));
        #pragma unroll
        for (int ky = 0; ky < 3; ky++) {
            unsigned long long r2[18];
            #pragma unroll
            for (int xi = 0; xi < 18; xi++)
                r2[xi] = *reinterpret_cast<const unsigned long long*>(&s_in[ky][xi][ci2*2]);
            #pragma unroll
            for (int kx = 0; kx < 3; kx++) {
                unsigned long long w = wv[ky*3 + kx];
                #pragma unroll
                for (int x = 0; x < 16; x++)
                    acc2[x] = ffma2(w, r2[x+kx], acc2[x]);
            }
        }
    }
    float bv = bias[co];
    #pragma unroll
    for (int x = 0; x < 16; x++) {
        float lo, hi;
        f2_unpack(acc2[x], lo, hi);
        float hval = s_in[1][x+1][co];
        g_h2[((b*16+y)*16+x)*128 + co] = 0.5f*hval + 0.5f*((lo + hi) + bv);
    }
}

// f_hat += h2; f_rest -= h2; sse_si += (f_hat - f)^2
__global__ void k_update(const float* __restrict__ a_, const float* __restrict__ b_, int si) {
    const float* f = g_swap ? b_ : a_;
    int i = blockIdx.x*256 + threadIdx.x;
    float h  = g_h2[i];
    float fh = g_fhat[i] + h;
    g_fhat[i]  = fh;
    g_frest[i] -= h;
    int c  = i & 127;
    int p  = i >> 7;
    int b  = p >> 8;
    int yx = p & 255;
    float fv = f[((b*128 + c) << 8) | yx];
    float d = fh - fv;
    float s = d*d;
    #pragma unroll
    for (int m = 16; m > 0; m >>= 1) s += __shfl_xor_sync(0xffffffffu, s, m);
    __shared__ float ws[8];
    int t = threadIdx.x;
    if ((t & 31) == 0) ws[t >> 5] = s;
    __syncthreads();
    if (t < 8) {
        float x = ws[t];
        #pragma unroll
        for (int m = 4; m > 0; m >>= 1) x += __shfl_xor_sync(0xffu, x, m);
        if (t == 0) atomicAdd(&g_sse[si], x);
    }
}

__global__ void k_final(float* __restrict__ out) {
    int i = blockIdx.x*256 + threadIdx.x;
    int b  = i >> 15;
    int c  = (i >> 8) & 127;
    int yx = i & 255;
    out[i] = g_fhat[((((b << 8) | yx) << 7) | c)];
    if (i == 0) {
        float L = 0.f;
        for (int s = 0; s < 5; s++) L += 1.25f * (g_sse[s] / (float)NELEM);
        out[NELEM] = L / 5.f;
    }
}

// ---------------- launch ----------------
extern "C" void kernel_launch(void* const* d_in, const int* in_sizes, int n_in,
                              void* d_out, int out_size) {
    // resolve inputs by size: phi_w=589824, phi_b=512; the two 1048576 inputs are
    // f/embedding in unknown order (device-side probe disambiguates).
    const float* cand0 = nullptr; const float* cand1 = nullptr;
    const float* pw = nullptr;    const float* pb = nullptr;
    for (int i = 0; i < n_in; i++) {
        int s = in_sizes[i];
        const float* p = (const float*)d_in[i];
        if      (s == 4*NCh*NCh*9) pw = p;
        else if (s == 4*NCh)       pb = p;
        else if (!cand0)           cand0 = p;
        else                       cand1 = p;
    }
    float* out = (float*)d_out;

    const int nn_smem = 64*65*8 + 64*132*4;  // Es2 (f32x2) + As = 67 KB -> opt-in
    cudaFuncSetAttribute(k_nn, cudaFuncAttributeMaxDynamicSharedMemorySize, nn_smem);

    k_detect<<<1, 256>>>(cand0);
    k_init_transpose<<<4096, 256>>>(cand0, cand1);
    k_init_esq<<<NV, 128>>>(cand0, cand1);
    k_init_wtrans<<<2304, 256>>>(pw);
    k_init_resizew<<<1, 128>>>();

    const int pns[5]  = {1, 2, 4, 8, 16};
    const int kphi[5] = {0, 1, 2, 2, 3};   // float64 tick tie resolves to 2 at si=2
    const int gys[5]  = {64, 64, 32, 16, 16};  // split-K factor per stage (V=8192)

    for (int si = 0; si < 5; si++) {
        int pn = pns[si];
        int N  = NB * pn * pn;
        int gy = gys[si];
        int iters = (NV / gy) / 64;
        int use_frest = (pn == 16);
        if (!use_frest) k_pool<<<N, 128>>>(pn);
        k_nn<<<dim3((N + 63)/64, gy), 256, nn_smem>>>(cand0, cand1, N, iters, use_frest);
        k_argmerge<<<(N + 255)/256, 256>>>(N, gy);
        k_upsample<<<NPOS, 128>>>(cand0, cand1, pn, si);
        k_conv<<<dim3(16, NB), 128>>>(pb + kphi[si]*NCh, kphi[si]);
        k_update<<<4096, 256>>>(cand0, cand1, si);
    }
    k_final<<<4096, 256>>>(out);
}

// round 4
// speedup vs baseline: 1.8628x; 1.0448x over previous
#include <cuda_runtime.h>
#include <cstdint>

#define NB 32
#define NCh 128
#define NHW 16
#define NV 8192
#define NELEM (NB*NCh*NHW*NHW)   // 1048576
#define NPOS  (NB*NHW*NHW)       // 8192

// ---------------- persistent device scratch (no allocation allowed) ----------------
__device__ float g_frest[NELEM];             // NHWC  (also the pn=16 query matrix)
__device__ float g_fhat[NELEM];              // NHWC
__device__ float g_f0[NELEM];                // NHWC copy of f (for loss/update)
__device__ float g_rest[NPOS*NCh];           // [N][128] query rows
__device__ float g_h[NELEM];                 // NHWC  (upsampled code field)
__device__ float g_half_esq[NV];
__device__ unsigned long long g_best[5*NPOS]; // per-stage packed (mono_score<<32 | ~idx)
__device__ float g_wT2[4*9*64*256];          // [k][ky*3+kx][ci2][co*2+{lo,hi}]
__device__ float g_Wall[5*16*16];            // resize weight matrices per stage
__device__ float g_sse[8];
__device__ int   g_swap;                     // 0: cand0 is f, 1: cand0 is embedding

// ---------------- f32x2 packed helpers ----------------
__device__ __forceinline__ unsigned long long f2_pack(float x, float y) {
    unsigned long long r;
    asm("mov.b64 %0, {%1, %2};" : "=l"(r) : "f"(x), "f"(y));
    return r;
}
__device__ __forceinline__ void f2_unpack(unsigned long long v, float& x, float& y) {
    asm("mov.b64 {%0, %1}, %2;" : "=f"(x), "=f"(y) : "l"(v));
}
__device__ __forceinline__ unsigned long long ffma2(unsigned long long a,
                                                    unsigned long long b,
                                                    unsigned long long c) {
    unsigned long long d;
    asm("fma.rn.f32x2 %0, %1, %2, %3;" : "=l"(d) : "l"(a), "l"(b), "l"(c));
    return d;
}
__device__ __forceinline__ unsigned long long pack_key(float sc, int col) {
    unsigned u = __float_as_uint(sc);
    u = (u & 0x80000000u) ? ~u : (u | 0x80000000u);   // monotone fp order
    return ((unsigned long long)u << 32) | (unsigned)(~col);  // ties -> smaller idx
}

// ---------------- input disambiguation (f vs embedding have equal sizes) ----------------
__global__ void k_detect(const float* __restrict__ a) {
    __shared__ float red[256];
    int t = threadIdx.x;
    float s = 0.f;
    #pragma unroll 4
    for (int k = 0; k < 64; k++) { float x = a[t + 256*k]; s += x*x; }
    red[t] = s; __syncthreads();
    for (int m = 128; m > 0; m >>= 1) { if (t < m) red[t] += red[t+m]; __syncthreads(); }
    // mean square of f ~ 1.0, of embedding ~ 0.25 over 16384 samples
    if (t == 0) g_swap = (red[0] > 0.5f * 16384.f) ? 0 : 1;
}

// ---------------- init kernels ----------------
__global__ void k_init_transpose(const float* __restrict__ a, const float* __restrict__ b) {
    const float* f = g_swap ? b : a;
    int i = blockIdx.x*blockDim.x + threadIdx.x;
    if (i < 8) g_sse[i] = 0.f;
    if (i < 5*NPOS) g_best[i] = 0ull;       // per-replay reset of argmin state
    if (i >= NELEM) return;
    int bb = i >> 15;            // /(128*256)
    int c  = (i >> 8) & 127;
    int yx = i & 255;
    int nh = ((((bb << 8) | yx) << 7) | c);
    float v = f[i];
    g_frest[nh] = v;
    g_f0[nh]    = v;
    g_fhat[nh]  = 0.f;
}

__global__ void k_init_esq(const float* __restrict__ a, const float* __restrict__ b) {
    const float* emb = g_swap ? a : b;
    int v = blockIdx.x;
    int t = threadIdx.x;  // 128
    float x = emb[v*NCh + t];
    float s = x*x;
    #pragma unroll
    for (int m = 16; m > 0; m >>= 1) s += __shfl_xor_sync(0xffffffffu, s, m);
    __shared__ float ws[4];
    if ((t & 31) == 0) ws[t >> 5] = s;
    __syncthreads();
    if (t == 0) g_half_esq[v] = 0.5f*(ws[0]+ws[1]+ws[2]+ws[3]);
}

// g_wT2[((k*9 + ky*3+kx)*64 + ci2)*256 + co*2 + p] = phi_w[k][co][ci2*2+p][ky][kx]
__global__ void k_init_wtrans(const float* __restrict__ phi_w) {
    int o = blockIdx.x*blockDim.x + threadIdx.x;
    if (o >= 4*NCh*NCh*9) return;
    int co2 = o & 255;
    int p  = co2 & 1;
    int co = co2 >> 1;
    int r  = o >> 8;
    int ci2 = r & 63; r >>= 6;
    int t9 = r % 9;
    int k  = r / 9;
    int ky = t9 / 3, kx = t9 % 3;
    int ci = ci2*2 + p;
    g_wT2[o] = phi_w[(((k*NCh + co)*NCh + ci)*3 + ky)*3 + kx];
}

__device__ __forceinline__ double keys_cubic(double x) {
    x = fabs(x);
    if (x < 1.0) return ((1.5*x - 2.5)*x)*x + 1.0;
    if (x < 2.0) return ((-0.5*x + 2.5)*x - 4.0)*x + 2.0;
    return 0.0;
}

// JAX compute_weight_mat: sample=(i+0.5)*in/out-0.5; Keys a=-0.5; column-normalized.
__global__ void k_init_resizew() {
    int t = threadIdx.x;     // need 80
    if (t >= 80) return;
    const int pns[5] = {1,2,4,8,16};
    int si = t >> 4, i = t & 15;
    int pn = pns[si];
    double sample = (i + 0.5) * (double)pn / 16.0 - 0.5;
    double w[16]; double tot = 0.0;
    for (int j = 0; j < 16; j++) w[j] = 0.0;
    for (int j = 0; j < pn; j++) { w[j] = keys_cubic(sample - (double)j); tot += w[j]; }
    for (int j = 0; j < 16; j++) g_Wall[(si*16 + i)*16 + j] = (float)(w[j] / tot);
}

// ---------------- stage kernels ----------------
// grid = N blocks, 128 threads. (not launched for pn==16)
__global__ void k_pool(int pn) {
    int n = blockIdx.x;
    int c = threadIdx.x;
    int s = 16 / pn;
    int pp = pn*pn;
    int b   = n / pp;
    int rem = n - b*pp;
    int py = rem / pn, px = rem - py*pn;
    float acc = 0.f;
    int y0 = py*s, x0 = px*s;
    for (int dy = 0; dy < s; dy++)
        for (int dx = 0; dx < s; dx++)
            acc += g_frest[(((b*16 + y0+dy)*16) + (x0+dx))*128 + c];
    g_rest[n*128 + c] = acc / (float)(s*s);
}

// NN search: argmax over V of (dot(r,e) - 0.5|e|^2)  <=>  argmin distance.
// block: 64 rows x 64-code inner tile, `iters` tiles per slab, f32x2 packed over k.
// per-(row) winner merged via packed-key atomicMax into g_best[si*NPOS + row].
__global__ __launch_bounds__(256) void k_nn(const float* __restrict__ a_,
                                            const float* __restrict__ b_,
                                            int N, int iters, int use_frest, int si) {
    const float* emb = g_swap ? a_ : b_;
    extern __shared__ unsigned long long smu[];
    unsigned long long* Es2 = smu;                    // [64 k2][65] float2 per code
    float* As = (float*)(smu + 64*65);                // [64 rows][132] floats
    const float* R = use_frest ? g_frest : g_rest;
    unsigned long long* best = g_best + (size_t)si*NPOS;

    int r0    = blockIdx.x * 64;
    int vbase = blockIdx.y * (iters * 64);
    int t = threadIdx.x;

    #pragma unroll
    for (int q = 0; q < 8; q++) {
        int idx4 = t + q*256;
        int row = idx4 >> 5;
        int k4  = idx4 & 31;
        float4 v = make_float4(0.f,0.f,0.f,0.f);
        int gr = r0 + row;
        if (gr < N) v = reinterpret_cast<const float4*>(R + (size_t)gr*128)[k4];
        *reinterpret_cast<float4*>(&As[row*132 + k4*4]) = v;
    }

    int tm = t >> 4, tv = t & 15;
    unsigned long long bkey[4];
    #pragma unroll
    for (int i = 0; i < 4; i++) bkey[i] = 0ull;

    for (int it = 0; it < iters; it++) {
        int v0 = vbase + it*64;
        __syncthreads();
        #pragma unroll
        for (int q = 0; q < 8; q++) {
            int idx4 = t + q*256;
            int code = idx4 & 63;
            int kc   = idx4 >> 6;      // 0..31 float4 chunks
            float4 v = reinterpret_cast<const float4*>(emb + (size_t)(v0+code)*128)[kc];
            Es2[(2*kc  )*65 + code] = f2_pack(v.x, v.y);
            Es2[(2*kc+1)*65 + code] = f2_pack(v.z, v.w);
        }
        __syncthreads();

        unsigned long long acc[4][4];
        #pragma unroll
        for (int i = 0; i < 4; i++)
            #pragma unroll
            for (int j = 0; j < 4; j++) acc[i][j] = 0ull;

        #pragma unroll 8
        for (int k2 = 0; k2 < 64; k2++) {
            unsigned long long a[4], e[4];
            #pragma unroll
            for (int i = 0; i < 4; i++)
                a[i] = *reinterpret_cast<const unsigned long long*>(&As[(tm*4+i)*132 + k2*2]);
            #pragma unroll
            for (int j = 0; j < 4; j++)
                e[j] = Es2[k2*65 + (tv + 16*j)];
            #pragma unroll
            for (int i = 0; i < 4; i++)
                #pragma unroll
                for (int j = 0; j < 4; j++)
                    acc[i][j] = ffma2(a[i], e[j], acc[i][j]);
        }

        #pragma unroll
        for (int j = 0; j < 4; j++) {
            int col = v0 + tv + 16*j;
            float hs = g_half_esq[col];
            #pragma unroll
            for (int i = 0; i < 4; i++) {
                float lo, hi;
                f2_unpack(acc[i][j], lo, hi);
                unsigned long long key = pack_key((lo + hi) - hs, col);
                if (key > bkey[i]) bkey[i] = key;
            }
        }
    }

    // reduce over the 16 tv lanes (stays inside each 16-lane group)
    #pragma unroll
    for (int m = 8; m >= 1; m >>= 1)
        #pragma unroll
        for (int i = 0; i < 4; i++) {
            unsigned long long o = __shfl_xor_sync(0xffffffffu, bkey[i], m);
            if (o > bkey[i]) bkey[i] = o;
        }
    if (tv == 0) {
        #pragma unroll
        for (int i = 0; i < 4; i++) {
            int gr = r0 + tm*4 + i;
            if (gr < N) atomicMax(&best[gr], bkey[i]);
        }
    }
}

// gather + separable-cubic upsample (pn=16 has identity weights -> pure gather)
__global__ void k_upsample(const float* __restrict__ a_, const float* __restrict__ b_,
                           int pn, int si) {
    const float* emb = g_swap ? a_ : b_;
    const unsigned long long* best = g_best + (size_t)si*NPOS;
    int blk = blockIdx.x;   // 8192 = (b,Y,X)
    int c = threadIdx.x;    // 128
    if (pn == 16) {
        unsigned id = ~(unsigned)best[blk];
        g_h[(size_t)blk*128 + c] = emb[(size_t)id*128 + c];
        return;
    }
    int b = blk >> 8;
    int Y = (blk >> 4) & 15;
    int X = blk & 15;
    const float* Wm = g_Wall + si*256;
    float acc = 0.f;
    for (int py = 0; py < pn; py++) {
        float wy = Wm[Y*16 + py];
        if (wy == 0.f) continue;
        for (int px = 0; px < pn; px++) {
            float wx = Wm[X*16 + px];
            if (wx == 0.f) continue;
            int n = (b*pn + py)*pn + px;
            unsigned id = ~(unsigned)best[n];
            acc += (wy*wx) * emb[(size_t)id*128 + c];
        }
    }
    g_h[(size_t)blk*128 + c] = acc;
}

// Phi + fused update: h2 = 0.5*h + 0.5*(conv3x3(h)+bias);
// f_hat += h2; f_rest -= h2; sse[si] += (f_hat - f)^2.
// grid (16 rows, 32 batch), 128 thr = co.  ci-paired f32x2 accumulation.
__global__ __launch_bounds__(128) void k_conv(const float* __restrict__ bias, int kphi, int si) {
    __shared__ float s_in[3][18][128];
    int y  = blockIdx.x;
    int b  = blockIdx.y;
    int co = threadIdx.x;
    const float* wbase = g_wT2 + (size_t)kphi*(9*64*256);

    #pragma unroll
    for (int ky = 0; ky < 3; ky++) {
        int yy = y + ky - 1;
        #pragma unroll
        for (int xi = 0; xi < 18; xi++) {
            int xx = xi - 1;
            float v = 0.f;
            if (yy >= 0 && yy < 16 && xx >= 0 && xx < 16)
                v = g_h[((b*16+yy)*16+xx)*128 + co];
            s_in[ky][xi][co] = v;
        }
    }
    __syncthreads();

    unsigned long long acc2[16];
    #pragma unroll
    for (int x = 0; x < 16; x++) acc2[x] = 0ull;

    for (int ci2 = 0; ci2 < 64; ci2++) {
        unsigned long long wv[9];
        #pragma unroll
        for (int t9 = 0; t9 < 9; t9++)
            wv[t9] = *reinterpret_cast<const unsigned long long*>(
                         wbase + ((size_t)(t9*64 + ci2)*256 + co*2));
        #pragma unroll
        for (int ky = 0; ky < 3; ky++) {
            unsigned long long r2[18];
            #pragma unroll
            for (int xi = 0; xi < 18; xi++)
                r2[xi] = *reinterpret_cast<const unsigned long long*>(&s_in[ky][xi][ci2*2]);
            #pragma unroll
            for (int kx = 0; kx < 3; kx++) {
                unsigned long long w = wv[ky*3 + kx];
                #pragma unroll
                for (int x = 0; x < 16; x++)
                    acc2[x] = ffma2(w, r2[x+kx], acc2[x]);
            }
        }
    }

    float bv = bias[co];
    float local = 0.f;
    #pragma unroll
    for (int x = 0; x < 16; x++) {
        float lo, hi;
        f2_unpack(acc2[x], lo, hi);
        float hval = s_in[1][x+1][co];
        float h2 = 0.5f*hval + 0.5f*((lo + hi) + bv);
        int idx = ((b*16+y)*16+x)*128 + co;
        float fh = g_fhat[idx] + h2;
        g_fhat[idx]  = fh;
        g_frest[idx] -= h2;
        float d = fh - g_f0[idx];
        local += d*d;
    }

    // block-wide reduction of loss contribution
    #pragma unroll
    for (int m = 16; m > 0; m >>= 1) local += __shfl_xor_sync(0xffffffffu, local, m);
    __shared__ float ws[4];
    if ((co & 31) == 0) ws[co >> 5] = local;
    __syncthreads();
    if (co == 0) atomicAdd(&g_sse[si], ws[0]+ws[1]+ws[2]+ws[3]);
}

__global__ void k_final(float* __restrict__ out) {
    int i = blockIdx.x*256 + threadIdx.x;
    int b  = i >> 15;
    int c  = (i >> 8) & 127;
    int yx = i & 255;
    out[i] = g_fhat[((((b << 8) | yx) << 7) | c)];
    if (i == 0) {
        float L = 0.f;
        for (int s = 0; s < 5; s++) L += 1.25f * (g_sse[s] / (float)NELEM);
        out[NELEM] = L / 5.f;
    }
}

// ---------------- launch ----------------
extern "C" void kernel_launch(void* const* d_in, const int* in_sizes, int n_in,
                              void* d_out, int out_size) {
    // resolve inputs by size: phi_w=589824, phi_b=512; the two 1048576 inputs are
    // f/embedding in unknown order (device-side probe disambiguates).
    const float* cand0 = nullptr; const float* cand1 = nullptr;
    const float* pw = nullptr;    const float* pb = nullptr;
    for (int i = 0; i < n_in; i++) {
        int s = in_sizes[i];
        const float* p = (const float*)d_in[i];
        if      (s == 4*NCh*NCh*9) pw = p;
        else if (s == 4*NCh)       pb = p;
        else if (!cand0)           cand0 = p;
        else                       cand1 = p;
    }
    float* out = (float*)d_out;

    const int nn_smem = 64*65*8 + 64*132*4;  // Es2 (f32x2) + As = 67 KB -> opt-in
    cudaFuncSetAttribute(k_nn, cudaFuncAttributeMaxDynamicSharedMemorySize, nn_smem);

    k_detect<<<1, 256>>>(cand0);
    k_init_transpose<<<4096, 256>>>(cand0, cand1);
    k_init_esq<<<NV, 128>>>(cand0, cand1);
    k_init_wtrans<<<2304, 256>>>(pw);
    k_init_resizew<<<1, 128>>>();

    const int pns[5]  = {1, 2, 4, 8, 16};
    const int kphi[5] = {0, 1, 2, 2, 3};      // float64 tick tie resolves to 2 at si=2
    const int gys[5]  = {128, 128, 64, 32, 16}; // split-K per stage (iters = 128/gy)

    for (int si = 0; si < 5; si++) {
        int pn = pns[si];
        int N  = NB * pn * pn;
        int gy = gys[si];
        int iters = (NV / gy) / 64;
        int use_frest = (pn == 16);
        if (!use_frest) k_pool<<<N, 128>>>(pn);
        k_nn<<<dim3((N + 63)/64, gy), 256, nn_smem>>>(cand0, cand1, N, iters, use_frest, si);
        k_upsample<<<NPOS, 128>>>(cand0, cand1, pn, si);
        k_conv<<<dim3(16, NB), 128>>>(pb + kphi[si]*NCh, kphi[si], si);
    }
    k_final<<<4096, 256>>>(out);
}